// round 1
// baseline (speedup 1.0000x reference)
#include <cuda_runtime.h>
#include <math.h>

#define Dm 1024
#define Fm 4096
#define Em 8
#define Tm 4096
#define MAXP (Tm * 2)

#define BM 128
#define BN 128
#define BK 8

// ---- scratch (device globals; no allocation allowed) ----
__device__ float g_H[(size_t)MAXP * Fm];   // GELU activations, compact rows
__device__ int   g_cnt[Em];
__device__ int   g_off[Em];
__device__ int   g_fill[Em];
__device__ int   g_tokid[MAXP];
__device__ float g_wt[MAXP];
__device__ int   g_te[Tm];                 // packed expert ids (e0 | e1<<8)
__device__ float g_tw[2 * Tm];             // routing weights

// ---------------- zero out + counters ----------------
__global__ void zero_kernel(float* __restrict__ out) {
    int i = blockIdx.x * blockDim.x + threadIdx.x;
    float4 z = make_float4(0.f, 0.f, 0.f, 0.f);
    ((float4*)out)[i] = z;
    if (blockIdx.x == 0 && threadIdx.x < Em) g_cnt[threadIdx.x] = 0;
}

// ---------------- router: logits -> top2 -> softmax ----------------
__global__ void route_kernel(const float* __restrict__ x,
                             const float* __restrict__ Wr,
                             const float* __restrict__ br) {
    int t = blockIdx.x;
    __shared__ float xs[Dm];
    __shared__ float logits[Em];
    for (int i = threadIdx.x; i < Dm; i += blockDim.x) xs[i] = x[(size_t)t * Dm + i];
    __syncthreads();
    int warp = threadIdx.x >> 5, lane = threadIdx.x & 31;
    if (warp < Em) {
        float s = 0.f;
        for (int d = lane; d < Dm; d += 32) s += xs[d] * Wr[d * Em + warp];
        #pragma unroll
        for (int o = 16; o; o >>= 1) s += __shfl_xor_sync(0xffffffffu, s, o);
        if (lane == 0) logits[warp] = s + br[warp];
    }
    __syncthreads();
    if (threadIdx.x == 0) {
        int i0 = 0; float v0 = logits[0];
        #pragma unroll
        for (int e = 1; e < Em; e++) if (logits[e] > v0) { v0 = logits[e]; i0 = e; }
        int i1 = -1; float v1 = -1e30f;
        #pragma unroll
        for (int e = 0; e < Em; e++) if (e != i0 && logits[e] > v1) { v1 = logits[e]; i1 = e; }
        // softmax over (v0, v1); v0 >= v1
        float e1 = expf(v1 - v0);
        float inv = 1.0f / (1.0f + e1);
        atomicAdd(&g_cnt[i0], 1);
        atomicAdd(&g_cnt[i1], 1);
        g_te[t] = i0 | (i1 << 8);
        g_tw[2 * t]     = inv;
        g_tw[2 * t + 1] = e1 * inv;
    }
}

// ---------------- tiny exclusive scan over 8 counts ----------------
__global__ void scan_kernel() {
    int o = 0;
    for (int e = 0; e < Em; e++) { g_off[e] = o; g_fill[e] = o; o += g_cnt[e]; }
}

// ---------------- scatter token ids into compact per-expert lists ----------------
__global__ void scatter_kernel() {
    int t = blockIdx.x * blockDim.x + threadIdx.x;
    if (t >= Tm) return;
    int p = g_te[t];
    int e0 = p & 255, e1 = p >> 8;
    int s0 = atomicAdd(&g_fill[e0], 1);
    g_tokid[s0] = t; g_wt[s0] = g_tw[2 * t];
    int s1 = atomicAdd(&g_fill[e1], 1);
    g_tokid[s1] = t; g_wt[s1] = g_tw[2 * t + 1];
}

// ---------------- GEMM1: H = GELU(Xg @ W1[e] + b1[e]) ----------------
__global__ __launch_bounds__(256) void ffn1_kernel(const float* __restrict__ x,
                                                   const float* __restrict__ W1,
                                                   const float* __restrict__ b1) {
    int e = blockIdx.z;
    int cnt = g_cnt[e];
    int mBase = blockIdx.y * BM;
    if (mBase >= cnt) return;
    int off = g_off[e];
    int nBase = blockIdx.x * BN;
    const float* Bp = W1 + (size_t)e * Dm * Fm;

    __shared__ float As[BK][BM];
    __shared__ float Bs[BK][BN];

    int tid = threadIdx.x;
    int aRow = tid >> 1;
    int aK = (tid & 1) * 4;
    int bK = tid >> 5;
    int bN = (tid & 31) * 4;
    int tx = tid & 15;
    int ty = tid >> 4;

    int mRow = mBase + aRow;
    const float* xrow = nullptr;
    if (mRow < cnt) xrow = x + (size_t)g_tokid[off + mRow] * Dm;

    float acc[8][8];
    #pragma unroll
    for (int i = 0; i < 8; i++)
        #pragma unroll
        for (int j = 0; j < 8; j++) acc[i][j] = 0.f;

    for (int k0 = 0; k0 < Dm; k0 += BK) {
        float4 av = xrow ? *(const float4*)(xrow + k0 + aK)
                         : make_float4(0.f, 0.f, 0.f, 0.f);
        As[aK + 0][aRow] = av.x; As[aK + 1][aRow] = av.y;
        As[aK + 2][aRow] = av.z; As[aK + 3][aRow] = av.w;
        *(float4*)&Bs[bK][bN] = *(const float4*)(Bp + (size_t)(k0 + bK) * Fm + nBase + bN);
        __syncthreads();
        #pragma unroll
        for (int k = 0; k < BK; k++) {
            float4 a0 = *(const float4*)&As[k][ty * 8];
            float4 a1 = *(const float4*)&As[k][ty * 8 + 4];
            float4 c0 = *(const float4*)&Bs[k][tx * 8];
            float4 c1 = *(const float4*)&Bs[k][tx * 8 + 4];
            float aF[8] = {a0.x, a0.y, a0.z, a0.w, a1.x, a1.y, a1.z, a1.w};
            float bF[8] = {c0.x, c0.y, c0.z, c0.w, c1.x, c1.y, c1.z, c1.w};
            #pragma unroll
            for (int i = 0; i < 8; i++)
                #pragma unroll
                for (int j = 0; j < 8; j++) acc[i][j] += aF[i] * bF[j];
        }
        __syncthreads();
    }

    #pragma unroll
    for (int i = 0; i < 8; i++) {
        int m = mBase + ty * 8 + i;
        if (m < cnt) {
            float* hrow = g_H + (size_t)(off + m) * Fm + nBase + tx * 8;
            const float* b1p = b1 + (size_t)e * Fm + nBase + tx * 8;
            #pragma unroll
            for (int j = 0; j < 8; j++) {
                float v = acc[i][j] + b1p[j];
                hrow[j] = 0.5f * v * (1.0f + erff(v * 0.70710678118654752440f));
            }
        }
    }
}

// ---------------- GEMM2: out[tok] += w * (H @ W2[e] + b2[e]) ----------------
__global__ __launch_bounds__(256) void ffn2_kernel(float* __restrict__ out,
                                                   const float* __restrict__ W2,
                                                   const float* __restrict__ b2) {
    int e = blockIdx.z;
    int cnt = g_cnt[e];
    int mBase = blockIdx.y * BM;
    if (mBase >= cnt) return;
    int off = g_off[e];
    int nBase = blockIdx.x * BN;
    const float* Bp = W2 + (size_t)e * Fm * Dm;

    __shared__ float As[BK][BM];
    __shared__ float Bs[BK][BN];

    int tid = threadIdx.x;
    int aRow = tid >> 1;
    int aK = (tid & 1) * 4;
    int bK = tid >> 5;
    int bN = (tid & 31) * 4;
    int tx = tid & 15;
    int ty = tid >> 4;

    int mRow = mBase + aRow;
    const float* hrow = nullptr;
    if (mRow < cnt) hrow = g_H + (size_t)(off + mRow) * Fm;

    float acc[8][8];
    #pragma unroll
    for (int i = 0; i < 8; i++)
        #pragma unroll
        for (int j = 0; j < 8; j++) acc[i][j] = 0.f;

    for (int k0 = 0; k0 < Fm; k0 += BK) {
        float4 av = hrow ? *(const float4*)(hrow + k0 + aK)
                         : make_float4(0.f, 0.f, 0.f, 0.f);
        As[aK + 0][aRow] = av.x; As[aK + 1][aRow] = av.y;
        As[aK + 2][aRow] = av.z; As[aK + 3][aRow] = av.w;
        *(float4*)&Bs[bK][bN] = *(const float4*)(Bp + (size_t)(k0 + bK) * Dm + nBase + bN);
        __syncthreads();
        #pragma unroll
        for (int k = 0; k < BK; k++) {
            float4 a0 = *(const float4*)&As[k][ty * 8];
            float4 a1 = *(const float4*)&As[k][ty * 8 + 4];
            float4 c0 = *(const float4*)&Bs[k][tx * 8];
            float4 c1 = *(const float4*)&Bs[k][tx * 8 + 4];
            float aF[8] = {a0.x, a0.y, a0.z, a0.w, a1.x, a1.y, a1.z, a1.w};
            float bF[8] = {c0.x, c0.y, c0.z, c0.w, c1.x, c1.y, c1.z, c1.w};
            #pragma unroll
            for (int i = 0; i < 8; i++)
                #pragma unroll
                for (int j = 0; j < 8; j++) acc[i][j] += aF[i] * bF[j];
        }
        __syncthreads();
    }

    #pragma unroll
    for (int i = 0; i < 8; i++) {
        int m = mBase + ty * 8 + i;
        if (m < cnt) {
            int slot = off + m;
            int tok = g_tokid[slot];
            float w = g_wt[slot];
            float* orow = out + (size_t)tok * Dm + nBase + tx * 8;
            const float* b2p = b2 + (size_t)e * Dm + nBase + tx * 8;
            #pragma unroll
            for (int j = 0; j < 8; j++) {
                atomicAdd(&orow[j], w * (acc[i][j] + b2p[j]));
            }
        }
    }
}

extern "C" void kernel_launch(void* const* d_in, const int* in_sizes, int n_in,
                              void* d_out, int out_size) {
    const float* x  = (const float*)d_in[0];
    const float* Wr = (const float*)d_in[1];
    const float* br = (const float*)d_in[2];
    const float* W1 = (const float*)d_in[3];
    const float* b1 = (const float*)d_in[4];
    const float* W2 = (const float*)d_in[5];
    const float* b2 = (const float*)d_in[6];
    float* out = (float*)d_out;

    // zero output + counters
    zero_kernel<<<(Tm * Dm / 4) / 256, 256>>>(out);
    // routing
    route_kernel<<<Tm, 256>>>(x, Wr, br);
    scan_kernel<<<1, 1>>>();
    scatter_kernel<<<(Tm + 255) / 256, 256>>>();
    // expert FFN (grouped GEMMs)
    dim3 g1(Fm / BN, Tm / BM, Em);
    ffn1_kernel<<<g1, 256>>>(x, W1, b1);
    dim3 g2(Dm / BN, Tm / BM, Em);
    ffn2_kernel<<<g2, 256>>>(out, W2, b2);
}

// round 4
// speedup vs baseline: 3.1589x; 3.1589x over previous
#include <cuda_runtime.h>
#include <cstdint>
#include <stdint.h>
#include <math.h>

#define Dm 1024
#define Fm 4096
#define Em 8
#define Tm 4096
#define MAXP (2 * Tm)
#define PADR 128

#define BM 128
#define BN 128
#define BK 16
#define AST (BK + 4)    // 20 floats  -> conflict-free A frag loads, 16B-aligned rows
#define BST (BN + 8)    // 136 floats -> conflict-free B frag loads, 16B-aligned rows

// ---- scratch (device globals; allocation is forbidden) ----
__device__ float g_Xg[(size_t)(MAXP + PADR) * Dm];  // gathered tokens (tf32-rounded)
__device__ float g_H [(size_t)(MAXP + PADR) * Fm];  // GELU activations (tf32-rounded)
__device__ float g_Y [(size_t)(MAXP + PADR) * Dm];  // expert outputs (unweighted)
__device__ int   g_cnt[Em];
__device__ int   g_off[Em];
__device__ int   g_fill[Em];
__device__ int   g_tokid[MAXP];
__device__ int   g_te[Tm];            // e0 | e1<<8
__device__ int   g_tslot[2 * Tm];     // slot of (token, k)
__device__ float g_tw[2 * Tm];        // routing weights

__device__ __forceinline__ unsigned f2tf32(float f) {
    unsigned r;
    asm("cvt.rna.tf32.f32 %0, %1;" : "=r"(r) : "f"(f));
    return r;
}
__device__ __forceinline__ float tf32r(float f) { return __uint_as_float(f2tf32(f)); }

// ---------------- init counters ----------------
__global__ void init_kernel() {
    if (threadIdx.x < Em) g_cnt[threadIdx.x] = 0;
}

// ---------------- router: logits -> top2 -> softmax ----------------
__global__ void route_kernel(const float* __restrict__ x,
                             const float* __restrict__ Wr,
                             const float* __restrict__ br) {
    int t = blockIdx.x;
    __shared__ float xs[Dm];
    __shared__ float logits[Em];
    for (int i = threadIdx.x; i < Dm; i += blockDim.x) xs[i] = x[(size_t)t * Dm + i];
    __syncthreads();
    int warp = threadIdx.x >> 5, lane = threadIdx.x & 31;
    if (warp < Em) {
        float s = 0.f;
        for (int d = lane; d < Dm; d += 32) s += xs[d] * Wr[d * Em + warp];
        #pragma unroll
        for (int o = 16; o; o >>= 1) s += __shfl_xor_sync(0xffffffffu, s, o);
        if (lane == 0) logits[warp] = s + br[warp];
    }
    __syncthreads();
    if (threadIdx.x == 0) {
        int i0 = 0; float v0 = logits[0];
        #pragma unroll
        for (int e = 1; e < Em; e++) if (logits[e] > v0) { v0 = logits[e]; i0 = e; }
        int i1 = -1; float v1 = -1e30f;
        #pragma unroll
        for (int e = 0; e < Em; e++) if (e != i0 && logits[e] > v1) { v1 = logits[e]; i1 = e; }
        float e1 = expf(v1 - v0);
        float inv = 1.0f / (1.0f + e1);
        atomicAdd(&g_cnt[i0], 1);
        atomicAdd(&g_cnt[i1], 1);
        g_te[t] = i0 | (i1 << 8);
        g_tw[2 * t]     = inv;
        g_tw[2 * t + 1] = e1 * inv;
    }
}

// ---------------- tiny exclusive scan over 8 counts ----------------
__global__ void scan_kernel() {
    int o = 0;
    for (int e = 0; e < Em; e++) { g_off[e] = o; g_fill[e] = o; o += g_cnt[e]; }
}

// ---------------- scatter token ids into compact per-expert slots ----------------
__global__ void scatter_kernel() {
    int t = blockIdx.x * blockDim.x + threadIdx.x;
    if (t >= Tm) return;
    int p = g_te[t];
    int e0 = p & 255, e1 = p >> 8;
    int s0 = atomicAdd(&g_fill[e0], 1);
    g_tokid[s0] = t; g_tslot[2 * t] = s0;
    int s1 = atomicAdd(&g_fill[e1], 1);
    g_tokid[s1] = t; g_tslot[2 * t + 1] = s1;
}

// ---------------- gather tokens into compact rows (tf32-rounded) ----------------
__global__ void gather_kernel(const float* __restrict__ x) {
    int s = blockIdx.x;
    int tok = g_tokid[s];
    float4 v = ((const float4*)(x + (size_t)tok * Dm))[threadIdx.x];
    float4 o;
    o.x = tf32r(v.x); o.y = tf32r(v.y); o.z = tf32r(v.z); o.w = tf32r(v.w);
    ((float4*)(g_Xg + (size_t)s * Dm))[threadIdx.x] = o;
}

// ---------------- tf32 mma.sync grouped GEMM ----------------
#define MMA_TF32(d, a, b)                                                     \
    asm volatile(                                                             \
        "mma.sync.aligned.m16n8k8.row.col.f32.tf32.tf32.f32 "                 \
        "{%0,%1,%2,%3}, {%4,%5,%6,%7}, {%8,%9}, {%0,%1,%2,%3};"               \
        : "+f"(d[0]), "+f"(d[1]), "+f"(d[2]), "+f"(d[3])                      \
        : "r"(a[0]), "r"(a[1]), "r"(a[2]), "r"(a[3]), "r"(b[0]), "r"(b[1]))

// PHASE1: A=g_Xg (K=Dm), B=W1[e] (Dm x Fm), O=g_H with bias+GELU+tf32-round
// PHASE2: A=g_H  (K=Fm), B=W2[e] (Fm x Dm), O=g_Y raw
template <bool PHASE1>
__global__ __launch_bounds__(256) void gemm_kernel(
    const float* __restrict__ Wp,     // W1 or W2 base
    const float* __restrict__ bias)   // b1 (unused for phase 2)
{
    const int lda = PHASE1 ? Dm : Fm;
    const int ldb = PHASE1 ? Fm : Dm;
    const int ldo = PHASE1 ? Fm : Dm;
    const int KT  = (PHASE1 ? Dm : Fm) / BK;

    int e = blockIdx.z;
    int cnt = g_cnt[e];
    int mBase = blockIdx.y * BM;
    if (mBase >= cnt) return;
    int off = g_off[e];
    int nBase = blockIdx.x * BN;

    const float* A  = (PHASE1 ? g_Xg : g_H) + (size_t)(off + mBase) * lda;
    const float* Bp = Wp + (size_t)e * (size_t)(PHASE1 ? Dm : Fm) * (size_t)ldb;
    float* O        = (PHASE1 ? g_H : g_Y);

    __shared__ float As[2][BM][AST];
    __shared__ float Bs[2][BK][BST];

    int tid = threadIdx.x;
    int wid = tid >> 5, lane = tid & 31;
    int wm = wid & 3, wn = wid >> 2;      // 4 x 2 warp grid, 32x64 per warp
    int r = lane >> 2, c = lane & 3;

    float acc[2][8][4];
    #pragma unroll
    for (int mi = 0; mi < 2; mi++)
        #pragma unroll
        for (int ni = 0; ni < 8; ni++)
            #pragma unroll
            for (int q = 0; q < 4; q++) acc[mi][ni][q] = 0.f;

    unsigned asb = (unsigned)__cvta_generic_to_shared(&As[0][0][0]);
    unsigned bsb = (unsigned)__cvta_generic_to_shared(&Bs[0][0][0]);

    // ---- stage loader (cp.async, 16B chunks) ----
    auto load_stage = [&](int ktIdx, int buf) {
        int k0 = ktIdx * BK;
        unsigned asx = asb + buf * (BM * AST * 4);
        unsigned bsx = bsb + buf * (BK * BST * 4);
        {
            // A tile: 128 rows x 16 cols = 512 chunks of 4 floats; 2 per thread
            int row0 = tid >> 2, kc0 = (tid & 3) * 4;
            const float* src0 = A + (size_t)row0 * lda + k0 + kc0;
            unsigned dst0 = asx + (unsigned)(row0 * AST + kc0) * 4u;
            asm volatile("cp.async.cg.shared.global [%0], [%1], 16;" :: "r"(dst0), "l"(src0));
            int ch1 = tid + 256;
            int row1 = ch1 >> 2, kc1 = (ch1 & 3) * 4;
            const float* src1 = A + (size_t)row1 * lda + k0 + kc1;
            unsigned dst1 = asx + (unsigned)(row1 * AST + kc1) * 4u;
            asm volatile("cp.async.cg.shared.global [%0], [%1], 16;" :: "r"(dst1), "l"(src1));
        }
        {
            // B tile: 16 rows x 128 cols = 512 chunks of 4 floats; 2 per thread
            int row0 = tid >> 5, nc0 = (tid & 31) * 4;
            const float* src0 = Bp + (size_t)(k0 + row0) * ldb + nBase + nc0;
            unsigned dst0 = bsx + (unsigned)(row0 * BST + nc0) * 4u;
            asm volatile("cp.async.cg.shared.global [%0], [%1], 16;" :: "r"(dst0), "l"(src0));
            int ch1 = tid + 256;
            int row1 = ch1 >> 5, nc1 = (ch1 & 31) * 4;
            const float* src1 = Bp + (size_t)(k0 + row1) * ldb + nBase + nc1;
            unsigned dst1 = bsx + (unsigned)(row1 * BST + nc1) * 4u;
            asm volatile("cp.async.cg.shared.global [%0], [%1], 16;" :: "r"(dst1), "l"(src1));
        }
        asm volatile("cp.async.commit_group;");
    };

    load_stage(0, 0);

    for (int kt = 0; kt < KT; ++kt) {
        int cur = kt & 1;
        if (kt + 1 < KT) {
            load_stage(kt + 1, cur ^ 1);
            asm volatile("cp.async.wait_group 1;");
        } else {
            asm volatile("cp.async.wait_group 0;");
        }
        __syncthreads();

        #pragma unroll
        for (int ks = 0; ks < 2; ++ks) {
            int kk = ks * 8;
            unsigned a[2][4];
            #pragma unroll
            for (int mi = 0; mi < 2; ++mi) {
                int m0 = wm * 32 + mi * 16 + r;
                a[mi][0] = __float_as_uint(As[cur][m0][kk + c]);
                a[mi][1] = __float_as_uint(As[cur][m0 + 8][kk + c]);
                a[mi][2] = __float_as_uint(As[cur][m0][kk + c + 4]);
                a[mi][3] = __float_as_uint(As[cur][m0 + 8][kk + c + 4]);
            }
            unsigned b[8][2];
            #pragma unroll
            for (int ni = 0; ni < 8; ++ni) {
                int n0 = wn * 64 + ni * 8 + r;
                b[ni][0] = f2tf32(Bs[cur][kk + c][n0]);
                b[ni][1] = f2tf32(Bs[cur][kk + c + 4][n0]);
            }
            #pragma unroll
            for (int mi = 0; mi < 2; ++mi)
                #pragma unroll
                for (int ni = 0; ni < 8; ++ni)
                    MMA_TF32(acc[mi][ni], a[mi], b[ni]);
        }
        __syncthreads();
    }

    // ---- epilogue ----
    #pragma unroll
    for (int mi = 0; mi < 2; ++mi) {
        #pragma unroll
        for (int half = 0; half < 2; ++half) {
            int m = wm * 32 + mi * 16 + r + half * 8;
            if (mBase + m < cnt) {
                float* orow = O + (size_t)(off + mBase + m) * ldo + nBase;
                #pragma unroll
                for (int ni = 0; ni < 8; ++ni) {
                    int col = wn * 64 + ni * 8 + 2 * c;
                    float v0 = acc[mi][ni][half * 2 + 0];
                    float v1 = acc[mi][ni][half * 2 + 1];
                    if (PHASE1) {
                        v0 += bias[(size_t)e * Fm + nBase + col];
                        v1 += bias[(size_t)e * Fm + nBase + col + 1];
                        v0 = 0.5f * v0 * (1.0f + erff(v0 * 0.70710678118654752440f));
                        v1 = 0.5f * v1 * (1.0f + erff(v1 * 0.70710678118654752440f));
                        v0 = tf32r(v0);
                        v1 = tf32r(v1);
                    }
                    *(float2*)(orow + col) = make_float2(v0, v1);
                }
            }
        }
    }
}

// ---------------- combine: out[t] = sum_k w_k * (Y[slot_k] + b2[e_k]) ----------------
__global__ void combine_kernel(float* __restrict__ out,
                               const float* __restrict__ b2) {
    int t = blockIdx.x;
    int p = g_te[t];
    int e0 = p & 255, e1 = p >> 8;
    float w0 = g_tw[2 * t], w1 = g_tw[2 * t + 1];
    int s0 = g_tslot[2 * t], s1 = g_tslot[2 * t + 1];
    int d = threadIdx.x;
    float4 y0 = ((const float4*)(g_Y + (size_t)s0 * Dm))[d];
    float4 y1 = ((const float4*)(g_Y + (size_t)s1 * Dm))[d];
    float4 c0 = ((const float4*)(b2 + (size_t)e0 * Dm))[d];
    float4 c1 = ((const float4*)(b2 + (size_t)e1 * Dm))[d];
    float4 o;
    o.x = w0 * (y0.x + c0.x) + w1 * (y1.x + c1.x);
    o.y = w0 * (y0.y + c0.y) + w1 * (y1.y + c1.y);
    o.z = w0 * (y0.z + c0.z) + w1 * (y1.z + c1.z);
    o.w = w0 * (y0.w + c0.w) + w1 * (y1.w + c1.w);
    ((float4*)(out + (size_t)t * Dm))[d] = o;
}

extern "C" void kernel_launch(void* const* d_in, const int* in_sizes, int n_in,
                              void* d_out, int out_size) {
    const float* x  = (const float*)d_in[0];
    const float* Wr = (const float*)d_in[1];
    const float* br = (const float*)d_in[2];
    const float* W1 = (const float*)d_in[3];
    const float* b1 = (const float*)d_in[4];
    const float* W2 = (const float*)d_in[5];
    const float* b2 = (const float*)d_in[6];
    float* out = (float*)d_out;

    init_kernel<<<1, 32>>>();
    route_kernel<<<Tm, 256>>>(x, Wr, br);
    scan_kernel<<<1, 1>>>();
    scatter_kernel<<<(Tm + 255) / 256, 256>>>();
    gather_kernel<<<MAXP, 256>>>(x);

    dim3 g1(Fm / BN, Tm / BM, Em);
    gemm_kernel<true><<<g1, 256>>>(W1, b1);
    dim3 g2(Dm / BN, Tm / BM, Em);
    gemm_kernel<false><<<g2, 256>>>(W2, b2);

    combine_kernel<<<Tm, 256>>>(out, b2);
}

// round 6
// speedup vs baseline: 5.0792x; 1.6079x over previous
#include <cuda_runtime.h>
#include <cuda_fp16.h>
#include <cstdint>
#include <stdint.h>
#include <math.h>

#define Dm 1024
#define Fm 4096
#define Em 8
#define Tm 4096
#define MAXP (2 * Tm)
#define PADR 128

#define BM 128
#define BN 128
#define BK 32
#define AST (BK + 8)   // 40 halfs = 80B rows -> conflict-free frag loads, 16B-aligned
#define BST (BK + 8)

// ---- scratch (device globals; allocation is forbidden) ----
__device__ __half g_W1h[(size_t)Em * Fm * Dm];      // W1 transposed fp16: [e][f][d]
__device__ __half g_W2h[(size_t)Em * Dm * Fm];      // W2 transposed fp16: [e][d][f]
__device__ __half g_Xg[(size_t)(MAXP + PADR) * Dm]; // gathered tokens fp16
__device__ __half g_H [(size_t)(MAXP + PADR) * Fm]; // GELU activations fp16
__device__ float  g_Y [(size_t)(MAXP + PADR) * Dm]; // expert outputs fp32
__device__ int   g_cnt[Em];
__device__ int   g_off[Em];
__device__ int   g_fill[Em];
__device__ int   g_tokid[MAXP];
__device__ int   g_te[Tm];            // e0 | e1<<8
__device__ int   g_tslot[2 * Tm];     // slot of (token, k)
__device__ float g_tw[2 * Tm];        // routing weights

// ---------------- init counters ----------------
__global__ void init_kernel() {
    if (threadIdx.x < Em) g_cnt[threadIdx.x] = 0;
}

// ---------------- router: logits -> top2 -> softmax ----------------
__global__ void route_kernel(const float* __restrict__ x,
                             const float* __restrict__ Wr,
                             const float* __restrict__ br) {
    int t = blockIdx.x;
    __shared__ float xs[Dm];
    __shared__ float logits[Em];
    for (int i = threadIdx.x; i < Dm; i += blockDim.x) xs[i] = x[(size_t)t * Dm + i];
    __syncthreads();
    int warp = threadIdx.x >> 5, lane = threadIdx.x & 31;
    if (warp < Em) {
        float s = 0.f;
        for (int d = lane; d < Dm; d += 32) s += xs[d] * Wr[d * Em + warp];
        #pragma unroll
        for (int o = 16; o; o >>= 1) s += __shfl_xor_sync(0xffffffffu, s, o);
        if (lane == 0) logits[warp] = s + br[warp];
    }
    __syncthreads();
    if (threadIdx.x == 0) {
        int i0 = 0; float v0 = logits[0];
        #pragma unroll
        for (int e = 1; e < Em; e++) if (logits[e] > v0) { v0 = logits[e]; i0 = e; }
        int i1 = -1; float v1 = -1e30f;
        #pragma unroll
        for (int e = 0; e < Em; e++) if (e != i0 && logits[e] > v1) { v1 = logits[e]; i1 = e; }
        float e1 = expf(v1 - v0);
        float inv = 1.0f / (1.0f + e1);
        atomicAdd(&g_cnt[i0], 1);
        atomicAdd(&g_cnt[i1], 1);
        g_te[t] = i0 | (i1 << 8);
        g_tw[2 * t]     = inv;
        g_tw[2 * t + 1] = e1 * inv;
    }
}

// ---------------- tiny exclusive scan over 8 counts ----------------
__global__ void scan_kernel() {
    int o = 0;
    for (int e = 0; e < Em; e++) { g_off[e] = o; g_fill[e] = o; o += g_cnt[e]; }
}

// ---------------- scatter token ids into compact per-expert slots ----------------
__global__ void scatter_kernel() {
    int t = blockIdx.x * blockDim.x + threadIdx.x;
    if (t >= Tm) return;
    int p = g_te[t];
    int e0 = p & 255, e1 = p >> 8;
    int s0 = atomicAdd(&g_fill[e0], 1);
    g_tokid[s0] = t; g_tslot[2 * t] = s0;
    int s1 = atomicAdd(&g_fill[e1], 1);
    g_tokid[s1] = t; g_tslot[2 * t + 1] = s1;
}

// ---------------- gather tokens into compact fp16 rows ----------------
__global__ void gather_kernel(const float* __restrict__ x) {
    int s = blockIdx.x;
    int tok = g_tokid[s];
    float4 v = ((const float4*)(x + (size_t)tok * Dm))[threadIdx.x];
    __half* row = g_Xg + (size_t)s * Dm + threadIdx.x * 4;
    *(__half2*)(row)     = __floats2half2_rn(v.x, v.y);
    *(__half2*)(row + 2) = __floats2half2_rn(v.z, v.w);
}

// ---------------- weight convert + transpose: [e][K][N] f32 -> [e][N][K] f16 ----------------
// IS_W1 selects the destination device global INSIDE device code (a __device__
// symbol must never be passed as a kernel argument from host code).
template <int K, int N, bool IS_W1>
__global__ void convert_w_kernel(const float* __restrict__ W) {
    __shared__ float tile[32][33];
    int e = blockIdx.z;
    int n0 = blockIdx.x * 32, k0 = blockIdx.y * 32;
    const float* src = W + (size_t)e * K * N;
    __half* dst = (IS_W1 ? g_W1h : g_W2h) + (size_t)e * K * N;
    int tx = threadIdx.x, ty = threadIdx.y;   // 32 x 8
    #pragma unroll
    for (int j = 0; j < 4; j++)
        tile[ty + j * 8][tx] = src[(size_t)(k0 + ty + j * 8) * N + n0 + tx];
    __syncthreads();
    #pragma unroll
    for (int j = 0; j < 4; j++)
        dst[(size_t)(n0 + ty + j * 8) * K + k0 + tx] = __float2half_rn(tile[tx][ty + j * 8]);
}

// ---------------- fp16 mma.sync grouped GEMM ----------------
#define MMA_F16(d, a, b)                                                      \
    asm volatile(                                                             \
        "mma.sync.aligned.m16n8k16.row.col.f32.f16.f16.f32 "                  \
        "{%0,%1,%2,%3}, {%4,%5,%6,%7}, {%8,%9}, {%0,%1,%2,%3};"               \
        : "+f"(d[0]), "+f"(d[1]), "+f"(d[2]), "+f"(d[3])                      \
        : "r"(a[0]), "r"(a[1]), "r"(a[2]), "r"(a[3]), "r"(b[0]), "r"(b[1]))

// PHASE1: A=g_Xg (K=Dm), B=g_W1h [e][F][D], O=g_H (bias+GELU, fp16)
// PHASE2: A=g_H  (K=Fm), B=g_W2h [e][D][F], O=g_Y (raw fp32)
template <bool PHASE1>
__global__ __launch_bounds__(256, 2) void gemm_kernel(const float* __restrict__ bias) {
    const int K   = PHASE1 ? Dm : Fm;
    const int Nt  = PHASE1 ? Fm : Dm;
    const int KT  = K / BK;

    int e = blockIdx.z;
    int cnt = g_cnt[e];
    int mBase = blockIdx.y * BM;
    if (mBase >= cnt) return;
    int off = g_off[e];
    int nBase = blockIdx.x * BN;

    const __half* A  = (PHASE1 ? g_Xg : g_H) + (size_t)(off + mBase) * K;
    const __half* Bp = (PHASE1 ? g_W1h : g_W2h) + (size_t)e * (size_t)K * (size_t)Nt
                       + (size_t)nBase * K;   // rows = n, cols = k

    __shared__ __half As[2][BM][AST];
    __shared__ __half Bs[2][BN][BST];

    int tid = threadIdx.x;
    int wid = tid >> 5, lane = tid & 31;
    int wm = wid & 3, wn = wid >> 2;      // 4 x 2 warp grid, 32(M) x 64(N) per warp
    int r = lane >> 2, c = lane & 3;

    float acc[2][8][4];
    #pragma unroll
    for (int mi = 0; mi < 2; mi++)
        #pragma unroll
        for (int ni = 0; ni < 8; ni++)
            #pragma unroll
            for (int q = 0; q < 4; q++) acc[mi][ni][q] = 0.f;

    unsigned asb = (unsigned)__cvta_generic_to_shared(&As[0][0][0]);
    unsigned bsb = (unsigned)__cvta_generic_to_shared(&Bs[0][0][0]);

    // stage loader: 128 rows x 32 halfs = 512 16B-chunks per tile, 2 per thread
    auto load_stage = [&](int ktIdx, int buf) {
        int k0 = ktIdx * BK;
        unsigned asx = asb + (unsigned)buf * (BM * AST * 2);
        unsigned bsx = bsb + (unsigned)buf * (BN * BST * 2);
        #pragma unroll
        for (int i = 0; i < 2; i++) {
            int ch = tid + i * 256;
            int row = ch >> 2, kc = (ch & 3) * 8;
            const __half* src = A + (size_t)row * K + k0 + kc;
            unsigned dst = asx + (unsigned)(row * AST + kc) * 2u;
            asm volatile("cp.async.cg.shared.global [%0], [%1], 16;" :: "r"(dst), "l"(src));
        }
        #pragma unroll
        for (int i = 0; i < 2; i++) {
            int ch = tid + i * 256;
            int row = ch >> 2, kc = (ch & 3) * 8;
            const __half* src = Bp + (size_t)row * K + k0 + kc;
            unsigned dst = bsx + (unsigned)(row * BST + kc) * 2u;
            asm volatile("cp.async.cg.shared.global [%0], [%1], 16;" :: "r"(dst), "l"(src));
        }
        asm volatile("cp.async.commit_group;");
    };

    load_stage(0, 0);

    for (int kt = 0; kt < KT; ++kt) {
        int cur = kt & 1;
        asm volatile("cp.async.wait_group 0;");
        __syncthreads();
        if (kt + 1 < KT) load_stage(kt + 1, cur ^ 1);

        #pragma unroll
        for (int ks = 0; ks < 2; ++ks) {
            int kk = ks * 16;
            unsigned a[2][4];
            #pragma unroll
            for (int mi = 0; mi < 2; ++mi) {
                int m0 = wm * 32 + mi * 16 + r;
                a[mi][0] = *(const unsigned*)&As[cur][m0][kk + 2 * c];
                a[mi][1] = *(const unsigned*)&As[cur][m0 + 8][kk + 2 * c];
                a[mi][2] = *(const unsigned*)&As[cur][m0][kk + 2 * c + 8];
                a[mi][3] = *(const unsigned*)&As[cur][m0 + 8][kk + 2 * c + 8];
            }
            unsigned b[8][2];
            #pragma unroll
            for (int ni = 0; ni < 8; ++ni) {
                int n0 = wn * 64 + ni * 8 + r;
                b[ni][0] = *(const unsigned*)&Bs[cur][n0][kk + 2 * c];
                b[ni][1] = *(const unsigned*)&Bs[cur][n0][kk + 2 * c + 8];
            }
            #pragma unroll
            for (int mi = 0; mi < 2; ++mi)
                #pragma unroll
                for (int ni = 0; ni < 8; ++ni)
                    MMA_F16(acc[mi][ni], a[mi], b[ni]);
        }
    }

    // ---- epilogue ----
    #pragma unroll
    for (int mi = 0; mi < 2; ++mi) {
        #pragma unroll
        for (int hh = 0; hh < 2; ++hh) {
            int m = wm * 32 + mi * 16 + r + hh * 8;
            if (mBase + m < cnt) {
                size_t slot = (size_t)(off + mBase + m);
                #pragma unroll
                for (int ni = 0; ni < 8; ++ni) {
                    int col = wn * 64 + ni * 8 + 2 * c;
                    float v0 = acc[mi][ni][hh * 2 + 0];
                    float v1 = acc[mi][ni][hh * 2 + 1];
                    if (PHASE1) {
                        v0 += bias[(size_t)e * Fm + nBase + col];
                        v1 += bias[(size_t)e * Fm + nBase + col + 1];
                        v0 = 0.5f * v0 * (1.0f + erff(v0 * 0.70710678118654752440f));
                        v1 = 0.5f * v1 * (1.0f + erff(v1 * 0.70710678118654752440f));
                        *(__half2*)(g_H + slot * Fm + nBase + col) = __floats2half2_rn(v0, v1);
                    } else {
                        *(float2*)(g_Y + slot * Dm + nBase + col) = make_float2(v0, v1);
                    }
                }
            }
        }
    }
}

// ---------------- combine: out[t] = sum_k w_k * (Y[slot_k] + b2[e_k]) ----------------
__global__ void combine_kernel(float* __restrict__ out,
                               const float* __restrict__ b2) {
    int t = blockIdx.x;
    int p = g_te[t];
    int e0 = p & 255, e1 = p >> 8;
    float w0 = g_tw[2 * t], w1 = g_tw[2 * t + 1];
    int s0 = g_tslot[2 * t], s1 = g_tslot[2 * t + 1];
    int d = threadIdx.x;
    float4 y0 = ((const float4*)(g_Y + (size_t)s0 * Dm))[d];
    float4 y1 = ((const float4*)(g_Y + (size_t)s1 * Dm))[d];
    float4 c0 = ((const float4*)(b2 + (size_t)e0 * Dm))[d];
    float4 c1 = ((const float4*)(b2 + (size_t)e1 * Dm))[d];
    float4 o;
    o.x = w0 * (y0.x + c0.x) + w1 * (y1.x + c1.x);
    o.y = w0 * (y0.y + c0.y) + w1 * (y1.y + c1.y);
    o.z = w0 * (y0.z + c0.z) + w1 * (y1.z + c1.z);
    o.w = w0 * (y0.w + c0.w) + w1 * (y1.w + c1.w);
    ((float4*)(out + (size_t)t * Dm))[d] = o;
}

extern "C" void kernel_launch(void* const* d_in, const int* in_sizes, int n_in,
                              void* d_out, int out_size) {
    const float* x  = (const float*)d_in[0];
    const float* Wr = (const float*)d_in[1];
    const float* br = (const float*)d_in[2];
    const float* W1 = (const float*)d_in[3];
    const float* b1 = (const float*)d_in[4];
    const float* W2 = (const float*)d_in[5];
    const float* b2 = (const float*)d_in[6];
    float* out = (float*)d_out;

    init_kernel<<<1, 32>>>();
    route_kernel<<<Tm, 256>>>(x, Wr, br);
    scan_kernel<<<1, 1>>>();
    scatter_kernel<<<(Tm + 255) / 256, 256>>>();
    gather_kernel<<<MAXP, 256>>>(x);

    // weight fp16 transpose-convert (destination globals resolved in device code)
    dim3 cb(32, 8);
    convert_w_kernel<Dm, Fm, true ><<<dim3(Fm / 32, Dm / 32, Em), cb>>>(W1);
    convert_w_kernel<Fm, Dm, false><<<dim3(Dm / 32, Fm / 32, Em), cb>>>(W2);

    dim3 g1(Fm / BN, Tm / BM, Em);
    gemm_kernel<true><<<g1, 256>>>(b1);
    dim3 g2(Dm / BN, Tm / BM, Em);
    gemm_kernel<false><<<g2, 256>>>(b2);

    combine_kernel<<<Tm, 256>>>(out, b2);
}

// round 8
// speedup vs baseline: 5.8688x; 1.1555x over previous
#include <cuda_runtime.h>
#include <cuda_fp16.h>
#include <cstdint>
#include <stdint.h>
#include <math.h>

#define Dm 1024
#define Fm 4096
#define Em 8
#define Tm 4096
#define MAXP (2 * Tm)
#define PADR 128

#define BM 128
#define BN 128
#define BK 32
#define AST (BK + 8)   // 40 halfs = 80B rows -> conflict-free ldmatrix, 16B-aligned
#define BST (BK + 8)

// ---- scratch (device globals; allocation is forbidden) ----
__device__ __half g_W1h[(size_t)Em * Fm * Dm];      // W1 transposed fp16: [e][f][d]
__device__ __half g_W2h[(size_t)Em * Dm * Fm];      // W2 transposed fp16: [e][d][f]
__device__ __half g_Xg[(size_t)(MAXP + PADR) * Dm]; // gathered tokens fp16
__device__ __half g_H [(size_t)(MAXP + PADR) * Fm]; // GELU activations fp16
__device__ float  g_Y [(size_t)(MAXP + PADR) * Dm]; // expert outputs fp32
__device__ int   g_cnt[Em];
__device__ int   g_off[Em];
__device__ int   g_fill[Em];
__device__ int   g_tokid[MAXP];
__device__ int   g_te[Tm];            // e0 | e1<<8
__device__ int   g_tslot[2 * Tm];     // slot of (token, k)
__device__ float g_tw[2 * Tm];        // routing weights

// ---------------- init counters ----------------
__global__ void init_kernel() {
    if (threadIdx.x < Em) g_cnt[threadIdx.x] = 0;
}

// ---------------- router: logits -> top2 -> softmax ----------------
__global__ void route_kernel(const float* __restrict__ x,
                             const float* __restrict__ Wr,
                             const float* __restrict__ br) {
    int t = blockIdx.x;
    __shared__ float xs[Dm];
    __shared__ float logits[Em];
    for (int i = threadIdx.x; i < Dm; i += blockDim.x) xs[i] = x[(size_t)t * Dm + i];
    __syncthreads();
    int warp = threadIdx.x >> 5, lane = threadIdx.x & 31;
    if (warp < Em) {
        float s = 0.f;
        for (int d = lane; d < Dm; d += 32) s += xs[d] * Wr[d * Em + warp];
        #pragma unroll
        for (int o = 16; o; o >>= 1) s += __shfl_xor_sync(0xffffffffu, s, o);
        if (lane == 0) logits[warp] = s + br[warp];
    }
    __syncthreads();
    if (threadIdx.x == 0) {
        int i0 = 0; float v0 = logits[0];
        #pragma unroll
        for (int e = 1; e < Em; e++) if (logits[e] > v0) { v0 = logits[e]; i0 = e; }
        int i1 = -1; float v1 = -1e30f;
        #pragma unroll
        for (int e = 0; e < Em; e++) if (e != i0 && logits[e] > v1) { v1 = logits[e]; i1 = e; }
        float e1 = expf(v1 - v0);
        float inv = 1.0f / (1.0f + e1);
        atomicAdd(&g_cnt[i0], 1);
        atomicAdd(&g_cnt[i1], 1);
        g_te[t] = i0 | (i1 << 8);
        g_tw[2 * t]     = inv;
        g_tw[2 * t + 1] = e1 * inv;
    }
}

// ---------------- tiny exclusive scan over 8 counts ----------------
__global__ void scan_kernel() {
    int o = 0;
    for (int e = 0; e < Em; e++) { g_off[e] = o; g_fill[e] = o; o += g_cnt[e]; }
}

// ---------------- scatter token ids into compact per-expert slots ----------------
__global__ void scatter_kernel() {
    int t = blockIdx.x * blockDim.x + threadIdx.x;
    if (t >= Tm) return;
    int p = g_te[t];
    int e0 = p & 255, e1 = p >> 8;
    int s0 = atomicAdd(&g_fill[e0], 1);
    g_tokid[s0] = t; g_tslot[2 * t] = s0;
    int s1 = atomicAdd(&g_fill[e1], 1);
    g_tokid[s1] = t; g_tslot[2 * t + 1] = s1;
}

// ---------------- gather tokens into compact fp16 rows ----------------
__global__ void gather_kernel(const float* __restrict__ x) {
    int s = blockIdx.x;
    int tok = g_tokid[s];
    float4 v = ((const float4*)(x + (size_t)tok * Dm))[threadIdx.x];
    __half* row = g_Xg + (size_t)s * Dm + threadIdx.x * 4;
    *(__half2*)(row)     = __floats2half2_rn(v.x, v.y);
    *(__half2*)(row + 2) = __floats2half2_rn(v.z, v.w);
}

// ---------------- weight convert + transpose: [e][K][N] f32 -> [e][N][K] f16 ----------------
template <int K, int N, bool IS_W1>
__global__ void convert_w_kernel(const float* __restrict__ W) {
    __shared__ float tile[32][33];
    int e = blockIdx.z;
    int n0 = blockIdx.x * 32, k0 = blockIdx.y * 32;
    const float* src = W + (size_t)e * K * N;
    __half* dst = (IS_W1 ? g_W1h : g_W2h) + (size_t)e * K * N;
    int tx = threadIdx.x, ty = threadIdx.y;   // 32 x 8
    #pragma unroll
    for (int j = 0; j < 4; j++)
        tile[ty + j * 8][tx] = src[(size_t)(k0 + ty + j * 8) * N + n0 + tx];
    __syncthreads();
    #pragma unroll
    for (int j = 0; j < 4; j++)
        dst[(size_t)(n0 + ty + j * 8) * K + k0 + tx] = __float2half_rn(tile[tx][ty + j * 8]);
}

// ---------------- fp16 mma.sync grouped GEMM (ldmatrix frag loads) ----------------
#define MMA_F16(d, a, b)                                                      \
    asm volatile(                                                             \
        "mma.sync.aligned.m16n8k16.row.col.f32.f16.f16.f32 "                  \
        "{%0,%1,%2,%3}, {%4,%5,%6,%7}, {%8,%9}, {%0,%1,%2,%3};"               \
        : "+f"(d[0]), "+f"(d[1]), "+f"(d[2]), "+f"(d[3])                      \
        : "r"(a[0]), "r"(a[1]), "r"(a[2]), "r"(a[3]), "r"(b[0]), "r"(b[1]))

#define LDSM4(r0, r1, r2, r3, addr)                                           \
    asm volatile("ldmatrix.sync.aligned.m8n8.x4.shared.b16 {%0,%1,%2,%3}, [%4];" \
                 : "=r"(r0), "=r"(r1), "=r"(r2), "=r"(r3) : "r"(addr))

// PHASE1: A=g_Xg (K=Dm), B=g_W1h [e][F][D], O=g_H (bias+GELU, fp16)
// PHASE2: A=g_H  (K=Fm), B=g_W2h [e][D][F], O=g_Y (raw fp32)
template <bool PHASE1>
__global__ __launch_bounds__(256, 2) void gemm_kernel(const float* __restrict__ bias) {
    const int K   = PHASE1 ? Dm : Fm;
    const int Nt  = PHASE1 ? Fm : Dm;
    const int KT  = K / BK;

    int e = blockIdx.z;
    int cnt = g_cnt[e];
    int mBase = blockIdx.y * BM;
    if (mBase >= cnt) return;
    int off = g_off[e];
    int nBase = blockIdx.x * BN;

    const __half* A  = (PHASE1 ? g_Xg : g_H) + (size_t)(off + mBase) * K;
    const __half* Bp = (PHASE1 ? g_W1h : g_W2h) + (size_t)e * (size_t)K * (size_t)Nt
                       + (size_t)nBase * K;   // rows = n, cols = k

    __shared__ __half As[2][BM][AST];
    __shared__ __half Bs[2][BN][BST];

    int tid = threadIdx.x;
    int wid = tid >> 5, lane = tid & 31;
    int wm = wid & 3, wn = wid >> 2;      // 4 x 2 warp grid, 32(M) x 64(N) per warp
    int r = lane >> 2, c = lane & 3;

    float acc[2][8][4];
    #pragma unroll
    for (int mi = 0; mi < 2; mi++)
        #pragma unroll
        for (int ni = 0; ni < 8; ni++)
            #pragma unroll
            for (int q = 0; q < 4; q++) acc[mi][ni][q] = 0.f;

    unsigned asb = (unsigned)__cvta_generic_to_shared(&As[0][0][0]);
    unsigned bsb = (unsigned)__cvta_generic_to_shared(&Bs[0][0][0]);

    // per-thread ldmatrix row addresses (byte offsets inside one stage)
    int q8 = lane >> 3, rr = lane & 7;
    // A matrices: reg j: row += (j&1)*8, col(k) += (j>>1)*8
    unsigned offA = (unsigned)(((wm * 32 + (q8 & 1) * 8 + rr) * AST + (q8 >> 1) * 8) * 2);
    // B matrices: reg j: n += (j>>1)*8, k += (j&1)*8
    unsigned offB = (unsigned)(((wn * 64 + (q8 >> 1) * 8 + rr) * BST + (q8 & 1) * 8) * 2);

    // stage loader: 128 rows x 32 halfs = 512 16B-chunks per tile, 2 per thread
    auto load_stage = [&](int ktIdx, int buf) {
        int k0 = ktIdx * BK;
        unsigned asx = asb + (unsigned)buf * (BM * AST * 2);
        unsigned bsx = bsb + (unsigned)buf * (BN * BST * 2);
        #pragma unroll
        for (int i = 0; i < 2; i++) {
            int ch = tid + i * 256;
            int row = ch >> 2, kc = (ch & 3) * 8;
            const __half* src = A + (size_t)row * K + k0 + kc;
            unsigned dst = asx + (unsigned)(row * AST + kc) * 2u;
            asm volatile("cp.async.cg.shared.global [%0], [%1], 16;" :: "r"(dst), "l"(src));
        }
        #pragma unroll
        for (int i = 0; i < 2; i++) {
            int ch = tid + i * 256;
            int row = ch >> 2, kc = (ch & 3) * 8;
            const __half* src = Bp + (size_t)row * K + k0 + kc;
            unsigned dst = bsx + (unsigned)(row * BST + kc) * 2u;
            asm volatile("cp.async.cg.shared.global [%0], [%1], 16;" :: "r"(dst), "l"(src));
        }
        asm volatile("cp.async.commit_group;");
    };

    load_stage(0, 0);

    for (int kt = 0; kt < KT; ++kt) {
        int cur = kt & 1;
        asm volatile("cp.async.wait_group 0;");
        __syncthreads();
        if (kt + 1 < KT) load_stage(kt + 1, cur ^ 1);

        unsigned aS = asb + (unsigned)cur * (BM * AST * 2) + offA;
        unsigned bS = bsb + (unsigned)cur * (BN * BST * 2) + offB;

        #pragma unroll
        for (int ks = 0; ks < 2; ++ks) {
            unsigned kkb = (unsigned)(ks * 16 * 2);   // byte offset of k-slice
            unsigned a[2][4];
            LDSM4(a[0][0], a[0][1], a[0][2], a[0][3], aS + kkb);
            LDSM4(a[1][0], a[1][1], a[1][2], a[1][3], aS + kkb + 16u * AST * 2u);
            unsigned b[8][2];
            #pragma unroll
            for (int g = 0; g < 4; ++g) {
                LDSM4(b[2 * g][0], b[2 * g][1], b[2 * g + 1][0], b[2 * g + 1][1],
                      bS + kkb + (unsigned)g * 16u * BST * 2u);
            }
            #pragma unroll
            for (int mi = 0; mi < 2; ++mi)
                #pragma unroll
                for (int ni = 0; ni < 8; ++ni)
                    MMA_F16(acc[mi][ni], a[mi], b[ni]);
        }
    }

    // ---- epilogue ----
    #pragma unroll
    for (int mi = 0; mi < 2; ++mi) {
        #pragma unroll
        for (int hh = 0; hh < 2; ++hh) {
            int m = wm * 32 + mi * 16 + r + hh * 8;
            if (mBase + m < cnt) {
                size_t slot = (size_t)(off + mBase + m);
                #pragma unroll
                for (int ni = 0; ni < 8; ++ni) {
                    int col = wn * 64 + ni * 8 + 2 * c;
                    float v0 = acc[mi][ni][hh * 2 + 0];
                    float v1 = acc[mi][ni][hh * 2 + 1];
                    if (PHASE1) {
                        v0 += bias[(size_t)e * Fm + nBase + col];
                        v1 += bias[(size_t)e * Fm + nBase + col + 1];
                        v0 = 0.5f * v0 * (1.0f + erff(v0 * 0.70710678118654752440f));
                        v1 = 0.5f * v1 * (1.0f + erff(v1 * 0.70710678118654752440f));
                        *(__half2*)(g_H + slot * Fm + nBase + col) = __floats2half2_rn(v0, v1);
                    } else {
                        *(float2*)(g_Y + slot * Dm + nBase + col) = make_float2(v0, v1);
                    }
                }
            }
        }
    }
}

// ---------------- combine: out[t] = sum_k w_k * (Y[slot_k] + b2[e_k]) ----------------
__global__ void combine_kernel(float* __restrict__ out,
                               const float* __restrict__ b2) {
    int t = blockIdx.x;
    int p = g_te[t];
    int e0 = p & 255, e1 = p >> 8;
    float w0 = g_tw[2 * t], w1 = g_tw[2 * t + 1];
    int s0 = g_tslot[2 * t], s1 = g_tslot[2 * t + 1];
    int d = threadIdx.x;
    float4 y0 = ((const float4*)(g_Y + (size_t)s0 * Dm))[d];
    float4 y1 = ((const float4*)(g_Y + (size_t)s1 * Dm))[d];
    float4 c0 = ((const float4*)(b2 + (size_t)e0 * Dm))[d];
    float4 c1 = ((const float4*)(b2 + (size_t)e1 * Dm))[d];
    float4 o;
    o.x = w0 * (y0.x + c0.x) + w1 * (y1.x + c1.x);
    o.y = w0 * (y0.y + c0.y) + w1 * (y1.y + c1.y);
    o.z = w0 * (y0.z + c0.z) + w1 * (y1.z + c1.z);
    o.w = w0 * (y0.w + c0.w) + w1 * (y1.w + c1.w);
    ((float4*)(out + (size_t)t * Dm))[d] = o;
}

extern "C" void kernel_launch(void* const* d_in, const int* in_sizes, int n_in,
                              void* d_out, int out_size) {
    const float* x  = (const float*)d_in[0];
    const float* Wr = (const float*)d_in[1];
    const float* br = (const float*)d_in[2];
    const float* W1 = (const float*)d_in[3];
    const float* b1 = (const float*)d_in[4];
    const float* W2 = (const float*)d_in[5];
    const float* b2 = (const float*)d_in[6];
    float* out = (float*)d_out;

    init_kernel<<<1, 32>>>();
    route_kernel<<<Tm, 256>>>(x, Wr, br);
    scan_kernel<<<1, 1>>>();
    scatter_kernel<<<(Tm + 255) / 256, 256>>>();
    gather_kernel<<<MAXP, 256>>>(x);

    dim3 cb(32, 8);
    convert_w_kernel<Dm, Fm, true ><<<dim3(Fm / 32, Dm / 32, Em), cb>>>(W1);
    convert_w_kernel<Fm, Dm, false><<<dim3(Dm / 32, Fm / 32, Em), cb>>>(W2);

    dim3 g1(Fm / BN, Tm / BM, Em);
    gemm_kernel<true><<<g1, 256>>>(b1);
    dim3 g2(Dm / BN, Tm / BM, Em);
    gemm_kernel<false><<<g2, 256>>>(b2);

    combine_kernel<<<Tm, 256>>>(out, b2);
}